// round 1
// baseline (speedup 1.0000x reference)
#include <cuda_runtime.h>
#include <cuda_bf16.h>
#include <cstddef>

// Problem constants
constexpr int Bc = 32, Lc = 256, Dc = 256, Hc = 256, Ec = 8, NLc = 4, KCONV = 4;
constexpr int BE  = Bc * Ec;                       // 256 independent sequences
constexpr long long MT   = (long long)BE * Lc;     // 65536 GEMM rows per layer
constexpr long long BELH = (long long)BE * Lc * Hc;// 16777216 output h elements

// Scratch (device globals: allocation-free per harness rules)
__device__ float g_ln [Bc * Lc * Dc];      // 8 MB
__device__ float g_u  [Bc * Lc * Dc];      // 8 MB
__device__ float g_pre[BE * Lc * Hc];      // 64 MB
__device__ float g_y  [BE * Lc * Hc];      // 64 MB

// ---------------------------------------------------------------------------
// Kernel 1: LayerNorm over D
// ---------------------------------------------------------------------------
__global__ void ln_kernel(const float* __restrict__ x,
                          const float* __restrict__ g,
                          const float* __restrict__ bt,
                          float* __restrict__ out)
{
    __shared__ float red[16];
    int m = blockIdx.x;          // b*L + l
    int d = threadIdx.x;         // 0..255
    float v = x[(size_t)m * Dc + d];
    float s1 = v, s2 = v * v;
    #pragma unroll
    for (int off = 16; off; off >>= 1) {
        s1 += __shfl_xor_sync(0xffffffffu, s1, off);
        s2 += __shfl_xor_sync(0xffffffffu, s2, off);
    }
    int w = d >> 5, lane = d & 31;
    if (lane == 0) { red[w] = s1; red[8 + w] = s2; }
    __syncthreads();
    float S1 = 0.f, S2 = 0.f;
    #pragma unroll
    for (int i = 0; i < 8; i++) { S1 += red[i]; S2 += red[8 + i]; }
    float mean = S1 * (1.0f / Dc);
    float var  = fmaxf(S2 * (1.0f / Dc) - mean * mean, 0.0f);
    out[(size_t)m * Dc + d] = (v - mean) * rsqrtf(var + 1e-5f) * g[d] + bt[d];
}

// ---------------------------------------------------------------------------
// Kernel 2: depthwise causal conv1d (K=4, left pad 3) + bias
// ---------------------------------------------------------------------------
__global__ void conv_kernel(const float* __restrict__ ln,
                            const float* __restrict__ cw,
                            const float* __restrict__ cb,
                            float* __restrict__ u)
{
    int m = blockIdx.x;          // b*L + l
    int d = threadIdx.x;
    int b = m / Lc, l = m % Lc;
    float acc = cb[d];
    #pragma unroll
    for (int k = 0; k < KCONV; k++) {
        int ls = l - (KCONV - 1) + k;
        if (ls >= 0)
            acc += cw[d * KCONV + k] * ln[((size_t)b * Lc + ls) * Dc + d];
    }
    u[(size_t)m * Dc + d] = acc;
}

// ---------------------------------------------------------------------------
// Kernel 3: input projection GEMM with batch-ensemble scaling
//   pre[m,h] = s[e,h] * ( sum_d X[m,d]*r[e,d]*W[h,d] ) + bvec[h]
//   m = (b*E + e)*L + l ;  layer-0 X is broadcast over e (bcast=1)
// ---------------------------------------------------------------------------
#define GBM 64
#define GBN 64
#define GBK 16
__global__ void __launch_bounds__(256)
gemm_pre_kernel(const float* __restrict__ X, int bcast,
                const float* __restrict__ W,
                const float* __restrict__ r_l,
                const float* __restrict__ s_l,
                const float* __restrict__ b_l,
                float* __restrict__ pre)
{
    __shared__ __align__(16) float As[GBK][GBM];
    __shared__ __align__(16) float Bs[GBK][GBN];

    int m0 = blockIdx.x * GBM;
    int h0 = blockIdx.y * GBN;
    int tid = threadIdx.x;
    int tx = tid & 15, ty = tid >> 4;

    // block is always inside one (b,e) slice: m0 multiple of 64, L=256
    int e_blk = (m0 / Lc) % Ec;
    int b_blk = m0 / (Ec * Lc);
    int l0    = m0 % Lc;

    int lr = tid >> 2, seg = tid & 3;   // loader mapping: row lr, 4-float segment seg
    const float* xrow = bcast ? (X + ((size_t)b_blk * Lc + (l0 + lr)) * Dc)
                              : (X + (size_t)(m0 + lr) * Dc);
    const float* rrow = r_l + e_blk * Dc;
    const float* wrow = W + (size_t)(h0 + lr) * Dc;

    float acc[4][4];
    #pragma unroll
    for (int i = 0; i < 4; i++)
        #pragma unroll
        for (int j = 0; j < 4; j++) acc[i][j] = 0.f;

    for (int d0 = 0; d0 < Dc; d0 += GBK) {
        float4 a4 = *(const float4*)(xrow + d0 + seg * 4);
        float4 r4 = *(const float4*)(rrow + d0 + seg * 4);
        float4 b4 = *(const float4*)(wrow + d0 + seg * 4);
        As[seg * 4 + 0][lr] = a4.x * r4.x;
        As[seg * 4 + 1][lr] = a4.y * r4.y;
        As[seg * 4 + 2][lr] = a4.z * r4.z;
        As[seg * 4 + 3][lr] = a4.w * r4.w;
        Bs[seg * 4 + 0][lr] = b4.x;
        Bs[seg * 4 + 1][lr] = b4.y;
        Bs[seg * 4 + 2][lr] = b4.z;
        Bs[seg * 4 + 3][lr] = b4.w;
        __syncthreads();
        #pragma unroll
        for (int kk = 0; kk < GBK; kk++) {
            float4 av = *(const float4*)&As[kk][ty * 4];
            float4 bv = *(const float4*)&Bs[kk][tx * 4];
            float a[4] = {av.x, av.y, av.z, av.w};
            float bb[4] = {bv.x, bv.y, bv.z, bv.w};
            #pragma unroll
            for (int i = 0; i < 4; i++)
                #pragma unroll
                for (int j = 0; j < 4; j++) acc[i][j] += a[i] * bb[j];
        }
        __syncthreads();
    }

    float4 s4 = *(const float4*)(s_l + (size_t)e_blk * Hc + h0 + tx * 4);
    float4 bi = *(const float4*)(b_l + h0 + tx * 4);
    #pragma unroll
    for (int i = 0; i < 4; i++) {
        float* orow = pre + (size_t)(m0 + ty * 4 + i) * Hc + h0 + tx * 4;
        float4 o;
        o.x = acc[i][0] * s4.x + bi.x;
        o.y = acc[i][1] * s4.y + bi.y;
        o.z = acc[i][2] * s4.z + bi.z;
        o.w = acc[i][3] * s4.w + bi.w;
        *(float4*)orow = o;
    }
}

// ---------------------------------------------------------------------------
// Kernel 4: persistent per-row recurrence.
//   Block handles rows {2*blk, 2*blk+1} (row = b*E + e). Thread k owns output
//   channel k. W_hh row k split: j in [0,128) in smem (padded float2 layout),
//   j in [128,256) in registers. Packed fp32x2 FMAs.
// ---------------------------------------------------------------------------
__device__ __forceinline__ unsigned long long ffma2(unsigned long long a,
                                                    unsigned long long b,
                                                    unsigned long long c)
{
    unsigned long long d;
    asm("fma.rn.f32x2 %0, %1, %2, %3;" : "=l"(d) : "l"(a), "l"(b), "l"(c));
    return d;
}

#define WLO_STRIDE 66                                  // float2 units (pad for 16B align)
#define RNN_SMEM_BYTES (256 * WLO_STRIDE * 8 + 2 * 2 * 256 * 4)

__global__ void __launch_bounds__(256, 1)
rnn_kernel(const float* __restrict__ pre,
           const float* __restrict__ Whh,
           float* __restrict__ y,
           float* __restrict__ hlast)
{
    extern __shared__ float sm[];
    float2* wlo = (float2*)sm;                          // [256][WLO_STRIDE]
    float*  hb  = sm + 256 * WLO_STRIDE * 2;            // [2 parity][2 rows][256]

    int k = threadIdx.x;
    int row0 = blockIdx.x * 2;
    int row1 = row0 + 1;

    // cooperative fill of low-half weights (j = 0..127 as 64 float2 pairs)
    for (int idx = k; idx < 256 * 64; idx += 256) {
        int kk = idx >> 6, jp = idx & 63;
        wlo[kk * WLO_STRIDE + jp] = *(const float2*)(Whh + (size_t)kk * Hc + 2 * jp);
    }
    // high-half weights (j = 128..255) into registers as packed pairs
    unsigned long long wreg[64];
    {
        const unsigned long long* wr =
            (const unsigned long long*)(Whh + (size_t)k * Hc + 128);
        #pragma unroll
        for (int jp = 0; jp < 64; jp++) wreg[jp] = wr[jp];
    }
    hb[0 * 512 + 0 * 256 + k] = 0.f;
    hb[0 * 512 + 1 * 256 + k] = 0.f;
    __syncthreads();

    const float* pre0 = pre + (size_t)row0 * Lc * Hc + k;
    const float* pre1 = pre + (size_t)row1 * Lc * Hc + k;
    float* y0 = y + (size_t)row0 * Lc * Hc + k;
    float* y1 = y + (size_t)row1 * Lc * Hc + k;
    const ulonglong2* wk2 = (const ulonglong2*)(wlo + (size_t)k * WLO_STRIDE);

    int p = 0;
    float cur0 = 0.f, cur1 = 0.f;
    #pragma unroll 1
    for (int t = 0; t < Lc; t++) {
        float pv0 = pre0[(size_t)t * Hc];
        float pv1 = pre1[(size_t)t * Hc];
        const ulonglong2* h0v = (const ulonglong2*)(hb + p * 512);
        const ulonglong2* h1v = (const ulonglong2*)(hb + p * 512 + 256);
        unsigned long long a0 = 0ull, a1 = 0ull;

        #pragma unroll
        for (int jq = 0; jq < 32; jq++) {           // j = 0..127 (smem weights)
            ulonglong2 wv  = wk2[jq];
            ulonglong2 hv0 = h0v[jq];
            ulonglong2 hv1 = h1v[jq];
            a0 = ffma2(wv.x, hv0.x, a0);
            a0 = ffma2(wv.y, hv0.y, a0);
            a1 = ffma2(wv.x, hv1.x, a1);
            a1 = ffma2(wv.y, hv1.y, a1);
        }
        #pragma unroll
        for (int jq = 0; jq < 32; jq++) {           // j = 128..255 (reg weights)
            ulonglong2 hv0 = h0v[32 + jq];
            ulonglong2 hv1 = h1v[32 + jq];
            a0 = ffma2(wreg[2 * jq],     hv0.x, a0);
            a0 = ffma2(wreg[2 * jq + 1], hv0.y, a0);
            a1 = ffma2(wreg[2 * jq],     hv1.x, a1);
            a1 = ffma2(wreg[2 * jq + 1], hv1.y, a1);
        }
        float s0 = pv0 + __uint_as_float((unsigned)a0) + __uint_as_float((unsigned)(a0 >> 32));
        float s1 = pv1 + __uint_as_float((unsigned)a1) + __uint_as_float((unsigned)(a1 >> 32));
        cur0 = tanhf(s0);
        cur1 = tanhf(s1);
        y0[(size_t)t * Hc] = cur0;
        y1[(size_t)t * Hc] = cur1;
        hb[(p ^ 1) * 512 + k]       = cur0;
        hb[(p ^ 1) * 512 + 256 + k] = cur1;
        __syncthreads();
        p ^= 1;
    }
    if (hlast) {
        hlast[(size_t)row0 * Hc + k] = cur0;
        hlast[(size_t)row1 * Hc + k] = cur1;
    }
}

// ---------------------------------------------------------------------------
// Launch
// ---------------------------------------------------------------------------
extern "C" void kernel_launch(void* const* d_in, const int* in_sizes, int n_in,
                              void* d_out, int out_size)
{
    const float* x      = (const float*)d_in[0];
    const float* conv_w = (const float*)d_in[1];
    const float* conv_b = (const float*)d_in[2];
    const float* ln_g   = (const float*)d_in[3];
    const float* ln_b   = (const float*)d_in[4];
    const float* W_ih   = (const float*)d_in[5];
    const float* W_hh   = (const float*)d_in[6];
    const float* r_in   = (const float*)d_in[7];
    const float* s_in   = (const float*)d_in[8];
    const float* b_in   = (const float*)d_in[9];

    float *p_ln, *p_u, *p_pre, *p_y;
    cudaGetSymbolAddress((void**)&p_ln,  g_ln);
    cudaGetSymbolAddress((void**)&p_u,   g_u);
    cudaGetSymbolAddress((void**)&p_pre, g_pre);
    cudaGetSymbolAddress((void**)&p_y,   g_y);

    cudaFuncSetAttribute(rnn_kernel,
                         cudaFuncAttributeMaxDynamicSharedMemorySize,
                         RNN_SMEM_BYTES);

    float* out = (float*)d_out;
    float* y_final;
    float* hlast;
    long long need = BELH + (long long)BE * Hc;
    if ((long long)out_size >= need)       { y_final = out;  hlast = out + BELH; }
    else if ((long long)out_size >= BELH)  { y_final = out;  hlast = nullptr; }
    else                                   { y_final = p_y;  hlast = out; }

    ln_kernel  <<<Bc * Lc, 256>>>(x, ln_g, ln_b, p_ln);
    conv_kernel<<<Bc * Lc, 256>>>(p_ln, conv_w, conv_b, p_u);

    dim3 ggrid((unsigned)(MT / GBM), Hc / GBN);
    for (int i = 0; i < NLc; i++) {
        const float* Xin = (i == 0) ? p_u : p_y;
        int bcast = (i == 0) ? 1 : 0;
        gemm_pre_kernel<<<ggrid, 256>>>(Xin, bcast,
                                        W_ih + (size_t)i * Hc * Dc,
                                        r_in + (size_t)i * Ec * Dc,
                                        s_in + (size_t)i * Ec * Hc,
                                        b_in + (size_t)i * Hc,
                                        p_pre);
        float* yout = (i == NLc - 1) ? y_final : p_y;
        float* hl   = (i == NLc - 1) ? hlast   : nullptr;
        rnn_kernel<<<BE / 2, 256, RNN_SMEM_BYTES>>>(p_pre,
                                                    W_hh + (size_t)i * Hc * Hc,
                                                    yout, hl);
    }
}